// round 16
// baseline (speedup 1.0000x reference)
#include <cuda_runtime.h>
#include <stdint.h>
#include <math.h>

typedef unsigned int u32;
typedef unsigned long long u64;

#define NB    8
#define NAC   22500
#define NG    20
#define PRE   2000
#define POST  300
#define NBLK  148
#define NTHR  1024
#define MASKB 128                // mask blocks (16 per image)
#define NLOSS 20                 // loss blocks in K3 (128..147)
#define NTOT  (NB*NAC)           // 180000
#define FULL  0xffffffffu
#define RING  64                 // smem row ring slots (k_p3)

// ---------------- device scratch (no allocations allowed) ----------------
__device__ float g_prop[NB*NAC*4];
__device__ u64   g_K[NB*NAC];
__device__ u64   g_R[NB*NAC];
__device__ int   g_lab[NB*NAC];
__device__ unsigned char g_arg[NB*NAC];
__device__ u64   g_gtblk[NBLK*NB*NG];   // per-block per-(b,g) best-anchor mins
__device__ int   g_npos[NB], g_nneg[NB];
__device__ u64   g_posthr[NB], g_negthr[NB];
__device__ float g_sbox[NB*PRE*4];
__device__ u32   g_nmsmask[NB*PRE*64];
__device__ double g_partC[NLOSS], g_partB[NLOSS];

// anchor dims, compile-time double math (bit-identical to 16.0*s*sqrt(r))
__constant__ float c_d0[9] = {
  (float)(16.0*8.0 *0x1.6a09e667f3bcdp-1), (float)(16.0*8.0),  (float)(16.0*8.0 *0x1.6a09e667f3bcdp+0),
  (float)(16.0*16.0*0x1.6a09e667f3bcdp-1), (float)(16.0*16.0), (float)(16.0*16.0*0x1.6a09e667f3bcdp+0),
  (float)(16.0*32.0*0x1.6a09e667f3bcdp-1), (float)(16.0*32.0), (float)(16.0*32.0*0x1.6a09e667f3bcdp+0)};
__constant__ float c_d1[9] = {
  (float)(16.0*8.0 *0x1.6a09e667f3bcdp+0), (float)(16.0*8.0),  (float)(16.0*8.0 *0x1.6a09e667f3bcdp-1),
  (float)(16.0*16.0*0x1.6a09e667f3bcdp+0), (float)(16.0*16.0), (float)(16.0*16.0*0x1.6a09e667f3bcdp-1),
  (float)(16.0*32.0*0x1.6a09e667f3bcdp+0), (float)(16.0*32.0), (float)(16.0*32.0*0x1.6a09e667f3bcdp-1)};

// ---------------- helpers ----------------
__device__ __forceinline__ u32 asc_map(float f){
    u32 b = __float_as_uint(f);
    return (b & 0x80000000u) ? ~b : (b | 0x80000000u);
}

__device__ __forceinline__ void anchor4(int n, float& x1, float& y1, float& x2, float& y2){
    int d = n / 2500, c = n % 2500;
    float d0 = c_d0[d], d1 = c_d1[d];
    float cx = (float)(8 + 16*(c/50));
    float cy = (float)(8 + 16*(c%50));
    float hx = __fmul_rn(0.5f, d0), hy = __fmul_rn(0.5f, d1);
    x1 = __fsub_rn(cx, hx); y1 = __fsub_rn(cy, hy);
    x2 = __fadd_rn(cx, hx); y2 = __fadd_rn(cy, hy);
}
__device__ __forceinline__ void anchor_ctr(int n, float& ax, float& ay, float& aw, float& ah){
    float x1, y1, x2, y2; anchor4(n, x1, y1, x2, y2);
    ax = __fmul_rn(__fadd_rn(x1,x2),0.5f);
    ay = __fmul_rn(__fadd_rn(y1,y2),0.5f);
    aw = __fsub_rn(x2,x1);
    ah = __fsub_rn(y2,y1);
}
__device__ __forceinline__ bool anchor_inside(int n){
    float x1, y1, x2, y2; anchor4(n, x1, y1, x2, y2);
    return (x1 >= 0.0f) && (y1 >= 0.0f) && (x2 <= 800.0f) && (y2 <= 800.0f);
}

__device__ __forceinline__ float iou_pair(float ax1,float ay1,float ax2,float ay2,
                                          float bx1,float by1,float bx2,float by2){
    float tlx = fmaxf(ax1,bx1), tly = fmaxf(ay1,by1);
    float brx = fminf(ax2,bx2), bry = fminf(ay2,by2);
    float w = fmaxf(__fsub_rn(brx, tlx), 0.0f);
    float h = fmaxf(__fsub_rn(bry, tly), 0.0f);
    float inter = __fmul_rn(w, h);
    float a1 = __fmul_rn(__fsub_rn(ax2,ax1), __fsub_rn(ay2,ay1));
    float a2 = __fmul_rn(__fsub_rn(bx2,bx1), __fsub_rn(by2,by1));
    float den = fmaxf(__fsub_rn(__fadd_rn(a1, a2), inter), 1e-8f);
    return __fdiv_rn(inter, den);
}

// jax threefry2x32, PARTITIONABLE scheme: counter i -> (0, i); out = x0 ^ x1.
#define TFR(r) { x0 += x1; x1 = (x1<<(r))|(x1>>(32-(r))); x1 ^= x0; }
__device__ __forceinline__ u32 tf_bits(u32 flat){
    const u32 k0 = 0u, k1 = 42u;
    const u32 k2 = 0x1BD11BDAu ^ k0 ^ k1;
    u32 x0 = 0u, x1 = flat;
    x0 += k0; x1 += k1;
    TFR(13) TFR(15) TFR(26) TFR(6)
    x0 += k1; x1 += k2 + 1u;
    TFR(17) TFR(29) TFR(16) TFR(24)
    x0 += k2; x1 += k0 + 2u;
    TFR(13) TFR(15) TFR(26) TFR(6)
    x0 += k0; x1 += k1 + 3u;
    TFR(17) TFR(29) TFR(16) TFR(24)
    x0 += k1; x1 += k2 + 4u;
    TFR(13) TFR(15) TFR(26) TFR(6)
    x0 += k2; x1 += k0 + 5u;
    return x0 ^ x1;
}
#undef TFR

// 4096-bin smem histogram: bin where cum count first reaches k (all threads).
__device__ u32 find_bin4k(const u32* __restrict__ hist, unsigned k,
                          u32* wsum, u32* s_bin){
    int tid = threadIdx.x, lane = tid & 31, wid = tid >> 5;
    u32 c0 = hist[tid*4+0], c1 = hist[tid*4+1], c2 = hist[tid*4+2], c3 = hist[tid*4+3];
    u32 mysum = c0 + c1 + c2 + c3;
    u32 v = mysum;
    #pragma unroll
    for (int o = 1; o < 32; o <<= 1){
        u32 t = __shfl_up_sync(FULL, v, o);
        if (lane >= o) v += t;
    }
    if (lane == 31) wsum[wid] = v;
    __syncthreads();
    if (wid == 0){
        u32 wv = wsum[lane];
        #pragma unroll
        for (int o = 1; o < 32; o <<= 1){
            u32 t = __shfl_up_sync(FULL, wv, o);
            if (lane >= o) wv += t;
        }
        wsum[lane] = wv;
    }
    __syncthreads();
    u32 offset = (wid > 0) ? wsum[wid-1] : 0u;
    u32 incl = v + offset;
    u32 excl = incl - mysum;
    if (excl < k && k <= incl){
        u32 cum = excl;
        if      (cum + c0 >= k) *s_bin = (u32)(tid*4+0);
        else if (cum + c0 + c1 >= k) *s_bin = (u32)(tid*4+1);
        else if (cum + c0 + c1 + c2 >= k) *s_bin = (u32)(tid*4+2);
        else *s_bin = (u32)(tid*4+3);
    }
    __syncthreads();
    return *s_bin;
}

template<int N>
__device__ void bitonic_sort(u64* buf, int tid, int nthr){
    for (unsigned k2 = 2; k2 <= (unsigned)N; k2 <<= 1){
        for (unsigned j = k2 >> 1; j > 0; j >>= 1){
            for (unsigned i = tid; i < (unsigned)N; i += nthr){
                unsigned ixj = i ^ j;
                if (ixj > i){
                    bool up = ((i & k2) == 0);
                    u64 a = buf[i], c = buf[ixj];
                    if ((a > c) == up){ buf[i] = c; buf[ixj] = a; }
                }
            }
            __syncthreads();
        }
    }
}

// ---------------- K1: decode + labels + rng + per-gt best (grid 148) -------
__global__ void __launch_bounds__(NTHR, 1)
k_p0(const float* __restrict__ pred, const float* __restrict__ cls,
     const float* __restrict__ gt){
    __shared__ float sgt[NB*NG*4];
    __shared__ u64 sbest[NB*NG];
    int blk = blockIdx.x, tid = threadIdx.x;
    int lane = tid & 31;
    if (tid < NB*NG*4) sgt[tid] = gt[tid];
    if (tid < NB*NG)   sbest[tid] = ~0ull;
    __syncthreads();

    const int stride = NBLK*NTHR;
    const int emax = ((NTOT + stride - 1)/stride)*stride;
    for (int e = blk*NTHR + tid; e < emax; e += stride){
        bool act = (e < NTOT);
        u32 actmask = __ballot_sync(FULL, act);
        if (!actmask) continue;
        int b = 0, n = 0;
        float bx1 = 0.f, by1 = 0.f, bx2 = 0.f, by2 = 0.f;
        const float* sg = sgt;
        if (act){
            b = e / NAC; n = e - b*NAC;
            int hw = n / 9, a = n % 9, h = hw / 50, w = hw % 50;
            size_t pbase = (((size_t)b*36 + (size_t)a*4)*50 + h)*50 + w;
            float dx = pred[pbase], dy = pred[pbase+2500];
            float dw = pred[pbase+5000], dh = pred[pbase+7500];
            float ax, ay, aw, ah; anchor_ctr(n, ax, ay, aw, ah);
            float px = __fadd_rn(ax, __fmul_rn(dx, aw));
            float py = __fadd_rn(ay, __fmul_rn(dy, ah));
            float pw = __fmul_rn(aw, expf(dw));
            float ph = __fmul_rn(ah, expf(dh));
            float hx = __fmul_rn(0.5f, pw), hy = __fmul_rn(0.5f, ph);
            float x1 = fminf(fmaxf(__fsub_rn(px, hx), 0.0f), 799.0f);
            float y1 = fminf(fmaxf(__fsub_rn(py, hy), 0.0f), 799.0f);
            float x2 = fminf(fmaxf(__fadd_rn(px, hx), 0.0f), 799.0f);
            float y2 = fminf(fmaxf(__fadd_rn(py, hy), 0.0f), 799.0f);
            *(float4*)(g_prop + (size_t)e*4) = make_float4(x1, y1, x2, y2);
            float sc = cls[(((size_t)b*18 + 9 + a)*50 + h)*50 + w];
            g_K[e] = ((u64)(~asc_map(sc)) << 32) | (u32)n;
            anchor4(n, bx1, by1, bx2, by2);
            sg = sgt + b*NG*4;
        }
        int lead = __ffs(actmask) - 1;
        int bl = __shfl_sync(FULL, b, lead);
        bool same = (!act) || (b == bl);
        bool uni = __all_sync(FULL, same);

        float best = -1.0f; int bg = 0;
        #pragma unroll
        for (int g = 0; g < NG; g++){
            float v = 0.0f;
            if (act){
                v = iou_pair(sg[g*4+0], sg[g*4+1], sg[g*4+2], sg[g*4+3],
                             bx1, by1, bx2, by2);
                if (v > best){ best = v; bg = g; }
            }
            if (uni){
                u32 bb = act ? __float_as_uint(v) : 0u;
                u32 mx = __reduce_max_sync(FULL, bb);
                u32 ball = __ballot_sync(FULL, act && (__float_as_uint(v) == mx));
                if (ball && lane == (__ffs(ball) - 1)){
                    u64 pk = (((u64)(~asc_map(v))) << 32) | (u32)n;
                    atomicMin((unsigned long long*)&sbest[bl*NG+g], (unsigned long long)pk);
                }
            } else if (act){
                u64 pk = (((u64)(~asc_map(v))) << 32) | (u32)n;
                atomicMin((unsigned long long*)&sbest[b*NG+g], (unsigned long long)pk);
            }
        }
        if (act){
            int lab = -1;
            if (best < 0.3f) lab = 0;
            if (best >= 0.7f) lab = 1;
            bool ins = (bx1 >= 0.0f) && (by1 >= 0.0f) && (bx2 <= 800.0f) && (by2 <= 800.0f);
            if (ins) lab = -1;
            g_lab[e] = lab;
            g_arg[e] = (unsigned char)bg;
            u32 bits = tf_bits((u32)e);
            g_R[e] = ((u64)(bits >> 9) << 32) | (u32)n;
        }
    }
    __syncthreads();
    if (tid < NB*NG) g_gtblk[blk*NB*NG + tid] = sbest[tid];
}

// ---------------- K2: topk (blocks 0-7) | select (blocks 8-23) -------------
__global__ void __launch_bounds__(NTHR, 1)
k_p1(){
    __shared__ union {
        struct { u64 buf[4096]; } tk;
        struct { u32 hist[4096]; u64 buf[512]; u64 tmp[NG]; } sel;
    } s;
    __shared__ u32 wsum[32];
    __shared__ u32 s_bin;
    __shared__ unsigned scnt;
    int blk = blockIdx.x, tid = threadIdx.x;
    int lane = tid & 31;

    if (blk < NB){
        int b = blk;
        const u64* keys = g_K + (size_t)b*NAC;
        u32* hist = (u32*)s.tk.buf;
        for (int i = tid; i < 4096; i += NTHR) hist[i] = 0;
        __syncthreads();
        for (int e = tid; e < NAC; e += NTHR)
            atomicAdd(&hist[(u32)(keys[e] >> 52)], 1u);
        __syncthreads();
        u32 B = find_bin4k(hist, (unsigned)PRE, wsum, &s_bin);
        __syncthreads();
        for (int i = tid; i < 4096; i += NTHR) s.tk.buf[i] = ~0ull;
        if (tid == 0) scnt = 0;
        __syncthreads();
        for (int e = tid; e < NAC; e += NTHR){
            u64 key = keys[e];
            if ((u32)(key >> 52) <= B){
                unsigned p = atomicAdd(&scnt, 1u);
                if (p < 4096) s.tk.buf[p] = key;
            }
        }
        __syncthreads();
        if (scnt <= 2048u) bitonic_sort<2048>(s.tk.buf, tid, NTHR);
        else               bitonic_sort<4096>(s.tk.buf, tid, NTHR);
        for (int t = tid; t < PRE; t += NTHR){
            int n = (int)(s.tk.buf[t] & 0xFFFFFFFFull);
            float4 v = *(const float4*)(g_prop + ((size_t)b*NAC + n)*4);
            *(float4*)(g_sbox + ((size_t)b*PRE + t)*4) = v;
        }
    } else {
        int b = (blk - 8) >> 1, c = (blk - 8) & 1;
        int* lab = g_lab + (size_t)b*NAC;
        const u64* R = g_R + (size_t)b*NAC;
        if (tid < NG) s.sel.tmp[tid] = ~0ull;
        __syncthreads();
        for (int i = tid; i < NBLK*NG; i += NTHR){
            int blkI = i / NG, g = i % NG;
            u64 v = g_gtblk[blkI*NB*NG + b*NG + g];
            if (v != ~0ull)
                atomicMin((unsigned long long*)&s.sel.tmp[g], (unsigned long long)v);
        }
        __syncthreads();
        if (tid < NG){
            int n = (int)(s.sel.tmp[tid] & 0xFFFFFFFFull);
            if (!anchor_inside(n)) lab[n] = 1;
        }
        for (int i = tid; i < 4096; i += NTHR) s.sel.hist[i] = 0;
        if (tid == 0) scnt = 0;
        __syncthreads();
        int want = (c == 0) ? 1 : 0;
        int cp = 0, cn = 0;
        for (int e = tid; e < NAC; e += NTHR){
            int l = lab[e];
            cp += (l == 1); cn += (l == 0);
            if (l == want) atomicAdd(&s.sel.hist[(u32)(R[e] >> 43)], 1u);
        }
        #pragma unroll
        for (int o = 16; o > 0; o >>= 1){
            cp += __shfl_down_sync(FULL, cp, o);
            cn += __shfl_down_sync(FULL, cn, o);
        }
        __shared__ int scp, scn;
        if (tid == 0){ scp = 0; scn = 0; }
        __syncthreads();
        if (lane == 0){ atomicAdd(&scp, cp); atomicAdd(&scn, cn); }
        __syncthreads();
        int np = min(scp, 128);
        int nn = min(scn, 256 - np);
        unsigned k = (c == 0) ? (unsigned)np : (unsigned)nn;
        u64 thr = 0;
        if (k > 0){
            u32 B = find_bin4k(s.sel.hist, k, wsum, &s_bin);
            for (int i = tid; i < 512; i += NTHR) s.sel.buf[i] = ~0ull;
            __syncthreads();
            for (int e = tid; e < NAC; e += NTHR){
                if (lab[e] != want) continue;
                u64 key = R[e];
                if ((u32)(key >> 43) <= B){
                    unsigned p = atomicAdd(&scnt, 1u);
                    if (p < 512) s.sel.buf[p] = key;
                }
            }
            __syncthreads();
            bitonic_sort<512>(s.sel.buf, tid, NTHR);
            thr = s.sel.buf[k-1];
        }
        if (tid == 0){
            if (c == 0){ g_posthr[b] = thr; g_npos[b] = np; }
            else       { g_negthr[b] = thr; g_nneg[b] = nn; }
        }
    }
}

// ---------------- K3: mask (0-127) | loss (128-147) ------------------------
__global__ void __launch_bounds__(NTHR, 1)
k_p2(const float* __restrict__ pred, const float* __restrict__ cls,
     const float* __restrict__ gt){
    __shared__ union {
        struct { float sx1[PRE], sy1[PRE], sx2[PRE], sy2[PRE]; } mk;
        struct { double s1[NTHR]; double s2[NTHR]; } ls;
    } s;
    int blk = blockIdx.x, tid = threadIdx.x;
    int lane = tid & 31;

    if (blk < MASKB){
        int b = blk >> 4;
        int q = blk & 15;
        const float* sb = g_sbox + (size_t)b*PRE*4;
        for (int j = tid; j < PRE; j += NTHR){
            float4 v = ((const float4*)sb)[j];
            s.mk.sx1[j]=v.x; s.mk.sy1[j]=v.y; s.mk.sx2[j]=v.z; s.mk.sy2[j]=v.w;
        }
        __syncthreads();
        int warp = tid >> 5;
        for (int t = q; t < 63; t += 16){
            int i = t*32 + warp;
            if (i >= PRE) continue;
            float ax1 = s.mk.sx1[i], ay1 = s.mk.sy1[i];
            float ax2 = s.mk.sx2[i], ay2 = s.mk.sy2[i];
            u32* rowout = g_nmsmask + ((size_t)b*PRE + i)*64;
            int cj0 = i >> 5;
            for (int cj = lane; cj < cj0; cj += 32) rowout[cj] = 0u;
            for (int cj = cj0; cj < 63; cj++){
                int j = cj*32 + lane;
                bool bit = false;
                if (j < PRE && j > i){
                    float iou = iou_pair(ax1, ay1, ax2, ay2,
                                         s.mk.sx1[j], s.mk.sy1[j],
                                         s.mk.sx2[j], s.mk.sy2[j]);
                    bit = iou > 0.7f;
                }
                u32 word = __ballot_sync(FULL, bit);
                if (lane == 0) rowout[cj] = word;
            }
            if (lane == 0) rowout[63] = 0u;
        }
    } else {
        int lblk = blk - MASKB;
        const int lstride = NLOSS*NTHR;
        double cacc = 0.0, bacc = 0.0;
        for (int e = lblk*NTHR + tid; e < NTOT; e += lstride){
            int b = e / NAC, n = e - b*NAC;
            int lab0 = g_lab[e];
            u64 R = g_R[e];
            int lab = -1;
            if (lab0 == 1 && g_npos[b] > 0 && R <= g_posthr[b]) lab = 1;
            else if (lab0 == 0 && g_nneg[b] > 0 && R <= g_negthr[b]) lab = 0;
            if (lab == -1) continue;
            int hw = n / 9, a = n % 9, h = hw / 50, w = hw % 50;
            {
                float x0 = cls[(((size_t)b*18 + a*2    )*50 + h)*50 + w];
                float x1 = cls[(((size_t)b*18 + a*2 + 1)*50 + h)*50 + w];
                float m = fmaxf(x0, x1);
                float l = logf(__fadd_rn(expf(__fsub_rn(x0, m)), expf(__fsub_rn(x1, m))));
                float sel = (lab == 1) ? x1 : x0;
                cacc += (double)__fsub_rn(l, __fsub_rn(sel, m));
            }
            if (lab == 1){
                float pd[4];
                size_t pbase = (((size_t)b*36 + (size_t)a*4)*50 + h)*50 + w;
                pd[0]=pred[pbase]; pd[1]=pred[pbase+2500];
                pd[2]=pred[pbase+5000]; pd[3]=pred[pbase+7500];
                float ax, ay, aw, ah; anchor_ctr(n, ax, ay, aw, ah);
                int gi = g_arg[e];
                const float* g4 = gt + ((size_t)b*NG + gi)*4;
                float gx = __fmul_rn(__fadd_rn(g4[0], g4[2]), 0.5f);
                float gy = __fmul_rn(__fadd_rn(g4[1], g4[3]), 0.5f);
                float gw = __fsub_rn(g4[2], g4[0]);
                float gh = __fsub_rn(g4[3], g4[1]);
                float tt[4];
                tt[0] = __fdiv_rn(__fsub_rn(gx, ax), aw);
                tt[1] = __fdiv_rn(__fsub_rn(gy, ay), ah);
                tt[2] = logf(__fdiv_rn(gw, aw));
                tt[3] = logf(__fdiv_rn(gh, ah));
                const float C1 = (float)(1.0/9.0), C2 = (float)(0.5/9.0);
                double sacc = 0.0;
                #pragma unroll
                for (int k2 = 0; k2 < 4; k2++){
                    float d = __fsub_rn(pd[k2], tt[k2]);
                    float ad = fabsf(d);
                    float l1 = (ad < C1) ? __fmul_rn(__fmul_rn(4.5f, d), d) : __fsub_rn(ad, C2);
                    sacc += (double)l1;
                }
                bacc += sacc;
            }
        }
        s.ls.s1[tid] = cacc; s.ls.s2[tid] = bacc;
        __syncthreads();
        for (int o = NTHR/2; o > 0; o >>= 1){
            if (tid < o){ s.ls.s1[tid] += s.ls.s1[tid+o]; s.ls.s2[tid] += s.ls.s2[tid+o]; }
            __syncthreads();
        }
        if (tid == 0){ g_partC[lblk] = s.ls.s1[0]; g_partB[lblk] = s.ls.s2[0]; }
    }
}

// ---------------- K4: ring-buffered NMS walk (0-7) | lossfin (8) -----------
// warps 1-3 stream mask rows into a 64-slot smem ring; warp 0 does the
// serial greedy walk reading rows from smem (LDS ~29cyc vs L2 ~250-600cyc).
__global__ void __launch_bounds__(128, 1)
k_p3(float* __restrict__ out){
    __shared__ u32 ring[RING][64];
    __shared__ volatile int slot_seq[RING];   // slot holds row r when == r+1
    __shared__ volatile int walker_cur;       // all rows < walker_cur are dead
    __shared__ int skeep[POST];
    int blk = blockIdx.x, tid = threadIdx.x;
    int wid = tid >> 5, lane = tid & 31;

    if (blk < NB){
        int b = blk;
        if (tid < RING) slot_seq[tid] = 0;
        if (tid == 0) walker_cur = 0;
        __syncthreads();
        const u32* mbase = g_nmsmask + (size_t)b*PRE*64;

        if (wid > 0){
            // ---- loader warps: stream rows (wid-1, wid-1+3, ...) ----
            for (int r = wid - 1; r < PRE; r += 3){
                if (lane == 0){
                    // slot r%RING may still hold row r-RING; wait till dead
                    while (walker_cur <= r - RING) __nanosleep(64);
                }
                __syncwarp();
                u64 v = __ldg((const u64*)(mbase + (size_t)r*64) + lane);
                *(u64*)&ring[r % RING][2*lane] = v;
                __syncwarp();
                __threadfence_block();
                if (lane == 0) slot_seq[r % RING] = r + 1;
            }
        } else {
            // ---- walker warp: serial greedy over smem rows ----
            u64 rem = (lane == 31) ? ~((1ull << (PRE - 1984)) - 1ull) : 0ull;
            int cnt = 0, cur = 0;
            while (cnt < POST){
                u64 myw = rem;
                int base = lane*64;
                if (cur >= base + 64) myw = ~0ull;
                else if (cur > base) myw |= ((1ull << (cur - base)) - 1ull);
                u32 bal = __ballot_sync(FULL, myw != ~0ull);
                if (!bal) break;
                int src = __ffs(bal) - 1;
                u64 w = __shfl_sync(FULL, myw, src);
                int bit = __ffsll((long long)~w) - 1;
                int i = src*64 + bit;
                if (lane == 0) skeep[cnt] = i;
                cnt++;
                if (cnt >= POST) break;
                // rows < i are dead; publish so loaders can run ahead
                if (lane == 0){
                    walker_cur = i;
                    while (slot_seq[i % RING] != i + 1) __nanosleep(32);
                }
                __syncwarp();
                __threadfence_block();
                u64 m = *(const u64*)&ring[i % RING][2*lane];
                rem |= m;
                cur = i + 1;
                if (lane == 0) walker_cur = cur;   // row i consumed
            }
            __syncwarp();
            if (lane == 0) walker_cur = PRE + RING;   // release loaders
            for (int j = lane; j < POST; j += 32){
                float4 v = make_float4(0.f, 0.f, 0.f, 0.f);
                if (j < cnt){
                    int i = skeep[j];
                    const float4 p = *(const float4*)(g_sbox + ((size_t)b*PRE + i)*4);
                    v = make_float4(floorf(p.x), floorf(p.y), floorf(p.z), floorf(p.w));
                }
                ((float4*)out)[b*POST + j] = v;
            }
        }
    } else if (tid == 0){
        double a = 0.0, c = 0.0;
        for (int i = 0; i < NLOSS; i++){ a += g_partC[i]; c += g_partB[i]; }
        int tot = 0;
        for (int b = 0; b < NB; b++) tot += g_npos[b] + g_nneg[b];
        if (tot < 1) tot = 1;
        int N0 = g_npos[0] + g_nneg[0];
        if (N0 < 1) N0 = 1;
        out[NB*POST*4 + 0] = (float)(c / (double)N0);   // bbox_loss
        out[NB*POST*4 + 1] = (float)(a / (double)tot);  // cls_loss
    }
}

// ---------------- launch: 4 kernels ----------------------------------------
extern "C" void kernel_launch(void* const* d_in, const int* in_sizes, int n_in,
                              void* d_out, int out_size){
    const float* pred = (const float*)d_in[0];
    const float* cls  = (const float*)d_in[1];
    const float* gt   = (const float*)d_in[2];
    float* out = (float*)d_out;
    (void)in_sizes; (void)n_in; (void)out_size;

    k_p0<<<NBLK, NTHR>>>(pred, cls, gt);
    k_p1<<<24, NTHR>>>();
    k_p2<<<NBLK, NTHR>>>(pred, cls, gt);
    k_p3<<<NB + 1, 128>>>(out);
}

// round 17
// speedup vs baseline: 2.4549x; 2.4549x over previous
#include <cuda_runtime.h>
#include <stdint.h>
#include <math.h>

typedef unsigned int u32;
typedef unsigned long long u64;

#define NB    8
#define NAC   22500
#define NG    20
#define PRE   2000
#define POST  300
#define NBLK  148
#define NTHR  1024
#define MASKB 128                // mask blocks (16 per image)
#define NLOSS 20                 // loss blocks in K3 (128..147)
#define NTOT  (NB*NAC)           // 180000
#define FULL  0xffffffffu
#define NWIN  32                 // ceil(PRE/64) windows in k_p3

// ---------------- device scratch (no allocations allowed) ----------------
__device__ float g_prop[NB*NAC*4];
__device__ u64   g_K[NB*NAC];
__device__ u64   g_R[NB*NAC];
__device__ int   g_lab[NB*NAC];
__device__ unsigned char g_arg[NB*NAC];
__device__ u64   g_gtblk[NBLK*NB*NG];   // per-block per-(b,g) best-anchor mins
__device__ int   g_npos[NB], g_nneg[NB];
__device__ u64   g_posthr[NB], g_negthr[NB];
__device__ float g_sbox[NB*PRE*4];
__device__ u32   g_nmsmask[NB*PRE*64];
__device__ double g_partC[NLOSS], g_partB[NLOSS];

// anchor dims, compile-time double math (bit-identical to 16.0*s*sqrt(r))
__constant__ float c_d0[9] = {
  (float)(16.0*8.0 *0x1.6a09e667f3bcdp-1), (float)(16.0*8.0),  (float)(16.0*8.0 *0x1.6a09e667f3bcdp+0),
  (float)(16.0*16.0*0x1.6a09e667f3bcdp-1), (float)(16.0*16.0), (float)(16.0*16.0*0x1.6a09e667f3bcdp+0),
  (float)(16.0*32.0*0x1.6a09e667f3bcdp-1), (float)(16.0*32.0), (float)(16.0*32.0*0x1.6a09e667f3bcdp+0)};
__constant__ float c_d1[9] = {
  (float)(16.0*8.0 *0x1.6a09e667f3bcdp+0), (float)(16.0*8.0),  (float)(16.0*8.0 *0x1.6a09e667f3bcdp-1),
  (float)(16.0*16.0*0x1.6a09e667f3bcdp+0), (float)(16.0*16.0), (float)(16.0*16.0*0x1.6a09e667f3bcdp-1),
  (float)(16.0*32.0*0x1.6a09e667f3bcdp+0), (float)(16.0*32.0), (float)(16.0*32.0*0x1.6a09e667f3bcdp-1)};

// ---------------- helpers ----------------
__device__ __forceinline__ u32 asc_map(float f){
    u32 b = __float_as_uint(f);
    return (b & 0x80000000u) ? ~b : (b | 0x80000000u);
}

__device__ __forceinline__ void anchor4(int n, float& x1, float& y1, float& x2, float& y2){
    int d = n / 2500, c = n % 2500;
    float d0 = c_d0[d], d1 = c_d1[d];
    float cx = (float)(8 + 16*(c/50));
    float cy = (float)(8 + 16*(c%50));
    float hx = __fmul_rn(0.5f, d0), hy = __fmul_rn(0.5f, d1);
    x1 = __fsub_rn(cx, hx); y1 = __fsub_rn(cy, hy);
    x2 = __fadd_rn(cx, hx); y2 = __fadd_rn(cy, hy);
}
__device__ __forceinline__ void anchor_ctr(int n, float& ax, float& ay, float& aw, float& ah){
    float x1, y1, x2, y2; anchor4(n, x1, y1, x2, y2);
    ax = __fmul_rn(__fadd_rn(x1,x2),0.5f);
    ay = __fmul_rn(__fadd_rn(y1,y2),0.5f);
    aw = __fsub_rn(x2,x1);
    ah = __fsub_rn(y2,y1);
}
__device__ __forceinline__ bool anchor_inside(int n){
    float x1, y1, x2, y2; anchor4(n, x1, y1, x2, y2);
    return (x1 >= 0.0f) && (y1 >= 0.0f) && (x2 <= 800.0f) && (y2 <= 800.0f);
}

__device__ __forceinline__ float iou_pair(float ax1,float ay1,float ax2,float ay2,
                                          float bx1,float by1,float bx2,float by2){
    float tlx = fmaxf(ax1,bx1), tly = fmaxf(ay1,by1);
    float brx = fminf(ax2,bx2), bry = fminf(ay2,by2);
    float w = fmaxf(__fsub_rn(brx, tlx), 0.0f);
    float h = fmaxf(__fsub_rn(bry, tly), 0.0f);
    float inter = __fmul_rn(w, h);
    float a1 = __fmul_rn(__fsub_rn(ax2,ax1), __fsub_rn(ay2,ay1));
    float a2 = __fmul_rn(__fsub_rn(bx2,bx1), __fsub_rn(by2,by1));
    float den = fmaxf(__fsub_rn(__fadd_rn(a1, a2), inter), 1e-8f);
    return __fdiv_rn(inter, den);
}

// jax threefry2x32, PARTITIONABLE scheme: counter i -> (0, i); out = x0 ^ x1.
#define TFR(r) { x0 += x1; x1 = (x1<<(r))|(x1>>(32-(r))); x1 ^= x0; }
__device__ __forceinline__ u32 tf_bits(u32 flat){
    const u32 k0 = 0u, k1 = 42u;
    const u32 k2 = 0x1BD11BDAu ^ k0 ^ k1;
    u32 x0 = 0u, x1 = flat;
    x0 += k0; x1 += k1;
    TFR(13) TFR(15) TFR(26) TFR(6)
    x0 += k1; x1 += k2 + 1u;
    TFR(17) TFR(29) TFR(16) TFR(24)
    x0 += k2; x1 += k0 + 2u;
    TFR(13) TFR(15) TFR(26) TFR(6)
    x0 += k0; x1 += k1 + 3u;
    TFR(17) TFR(29) TFR(16) TFR(24)
    x0 += k1; x1 += k2 + 4u;
    TFR(13) TFR(15) TFR(26) TFR(6)
    x0 += k2; x1 += k0 + 5u;
    return x0 ^ x1;
}
#undef TFR

// 4096-bin smem histogram: bin where cum count first reaches k (all threads).
__device__ u32 find_bin4k(const u32* __restrict__ hist, unsigned k,
                          u32* wsum, u32* s_bin){
    int tid = threadIdx.x, lane = tid & 31, wid = tid >> 5;
    u32 c0 = hist[tid*4+0], c1 = hist[tid*4+1], c2 = hist[tid*4+2], c3 = hist[tid*4+3];
    u32 mysum = c0 + c1 + c2 + c3;
    u32 v = mysum;
    #pragma unroll
    for (int o = 1; o < 32; o <<= 1){
        u32 t = __shfl_up_sync(FULL, v, o);
        if (lane >= o) v += t;
    }
    if (lane == 31) wsum[wid] = v;
    __syncthreads();
    if (wid == 0){
        u32 wv = wsum[lane];
        #pragma unroll
        for (int o = 1; o < 32; o <<= 1){
            u32 t = __shfl_up_sync(FULL, wv, o);
            if (lane >= o) wv += t;
        }
        wsum[lane] = wv;
    }
    __syncthreads();
    u32 offset = (wid > 0) ? wsum[wid-1] : 0u;
    u32 incl = v + offset;
    u32 excl = incl - mysum;
    if (excl < k && k <= incl){
        u32 cum = excl;
        if      (cum + c0 >= k) *s_bin = (u32)(tid*4+0);
        else if (cum + c0 + c1 >= k) *s_bin = (u32)(tid*4+1);
        else if (cum + c0 + c1 + c2 >= k) *s_bin = (u32)(tid*4+2);
        else *s_bin = (u32)(tid*4+3);
    }
    __syncthreads();
    return *s_bin;
}

template<int N>
__device__ void bitonic_sort(u64* buf, int tid, int nthr){
    for (unsigned k2 = 2; k2 <= (unsigned)N; k2 <<= 1){
        for (unsigned j = k2 >> 1; j > 0; j >>= 1){
            for (unsigned i = tid; i < (unsigned)N; i += nthr){
                unsigned ixj = i ^ j;
                if (ixj > i){
                    bool up = ((i & k2) == 0);
                    u64 a = buf[i], c = buf[ixj];
                    if ((a > c) == up){ buf[i] = c; buf[ixj] = a; }
                }
            }
            __syncthreads();
        }
    }
}

// ---------------- K1: decode + labels + rng + per-gt best (grid 148) -------
__global__ void __launch_bounds__(NTHR, 1)
k_p0(const float* __restrict__ pred, const float* __restrict__ cls,
     const float* __restrict__ gt){
    __shared__ float sgt[NB*NG*4];
    __shared__ u64 sbest[NB*NG];
    int blk = blockIdx.x, tid = threadIdx.x;
    int lane = tid & 31;
    if (tid < NB*NG*4) sgt[tid] = gt[tid];
    if (tid < NB*NG)   sbest[tid] = ~0ull;
    __syncthreads();

    const int stride = NBLK*NTHR;
    const int emax = ((NTOT + stride - 1)/stride)*stride;
    for (int e = blk*NTHR + tid; e < emax; e += stride){
        bool act = (e < NTOT);
        u32 actmask = __ballot_sync(FULL, act);
        if (!actmask) continue;
        int b = 0, n = 0;
        float bx1 = 0.f, by1 = 0.f, bx2 = 0.f, by2 = 0.f;
        const float* sg = sgt;
        if (act){
            b = e / NAC; n = e - b*NAC;
            int hw = n / 9, a = n % 9, h = hw / 50, w = hw % 50;
            size_t pbase = (((size_t)b*36 + (size_t)a*4)*50 + h)*50 + w;
            float dx = pred[pbase], dy = pred[pbase+2500];
            float dw = pred[pbase+5000], dh = pred[pbase+7500];
            float ax, ay, aw, ah; anchor_ctr(n, ax, ay, aw, ah);
            float px = __fadd_rn(ax, __fmul_rn(dx, aw));
            float py = __fadd_rn(ay, __fmul_rn(dy, ah));
            float pw = __fmul_rn(aw, expf(dw));
            float ph = __fmul_rn(ah, expf(dh));
            float hx = __fmul_rn(0.5f, pw), hy = __fmul_rn(0.5f, ph);
            float x1 = fminf(fmaxf(__fsub_rn(px, hx), 0.0f), 799.0f);
            float y1 = fminf(fmaxf(__fsub_rn(py, hy), 0.0f), 799.0f);
            float x2 = fminf(fmaxf(__fadd_rn(px, hx), 0.0f), 799.0f);
            float y2 = fminf(fmaxf(__fadd_rn(py, hy), 0.0f), 799.0f);
            *(float4*)(g_prop + (size_t)e*4) = make_float4(x1, y1, x2, y2);
            float sc = cls[(((size_t)b*18 + 9 + a)*50 + h)*50 + w];
            g_K[e] = ((u64)(~asc_map(sc)) << 32) | (u32)n;
            anchor4(n, bx1, by1, bx2, by2);
            sg = sgt + b*NG*4;
        }
        int lead = __ffs(actmask) - 1;
        int bl = __shfl_sync(FULL, b, lead);
        bool same = (!act) || (b == bl);
        bool uni = __all_sync(FULL, same);

        float best = -1.0f; int bg = 0;
        #pragma unroll
        for (int g = 0; g < NG; g++){
            float v = 0.0f;
            if (act){
                v = iou_pair(sg[g*4+0], sg[g*4+1], sg[g*4+2], sg[g*4+3],
                             bx1, by1, bx2, by2);
                if (v > best){ best = v; bg = g; }
            }
            if (uni){
                u32 bb = act ? __float_as_uint(v) : 0u;
                u32 mx = __reduce_max_sync(FULL, bb);
                u32 ball = __ballot_sync(FULL, act && (__float_as_uint(v) == mx));
                if (ball && lane == (__ffs(ball) - 1)){
                    u64 pk = (((u64)(~asc_map(v))) << 32) | (u32)n;
                    atomicMin((unsigned long long*)&sbest[bl*NG+g], (unsigned long long)pk);
                }
            } else if (act){
                u64 pk = (((u64)(~asc_map(v))) << 32) | (u32)n;
                atomicMin((unsigned long long*)&sbest[b*NG+g], (unsigned long long)pk);
            }
        }
        if (act){
            int lab = -1;
            if (best < 0.3f) lab = 0;
            if (best >= 0.7f) lab = 1;
            bool ins = (bx1 >= 0.0f) && (by1 >= 0.0f) && (bx2 <= 800.0f) && (by2 <= 800.0f);
            if (ins) lab = -1;
            g_lab[e] = lab;
            g_arg[e] = (unsigned char)bg;
            u32 bits = tf_bits((u32)e);
            g_R[e] = ((u64)(bits >> 9) << 32) | (u32)n;
        }
    }
    __syncthreads();
    if (tid < NB*NG) g_gtblk[blk*NB*NG + tid] = sbest[tid];
}

// ---------------- K2: topk (blocks 0-7) | select (blocks 8-23) -------------
__global__ void __launch_bounds__(NTHR, 1)
k_p1(){
    __shared__ union {
        struct { u64 buf[4096]; } tk;
        struct { u32 hist[4096]; u64 buf[512]; u64 tmp[NG]; } sel;
    } s;
    __shared__ u32 wsum[32];
    __shared__ u32 s_bin;
    __shared__ unsigned scnt;
    int blk = blockIdx.x, tid = threadIdx.x;
    int lane = tid & 31;

    if (blk < NB){
        int b = blk;
        const u64* keys = g_K + (size_t)b*NAC;
        u32* hist = (u32*)s.tk.buf;
        for (int i = tid; i < 4096; i += NTHR) hist[i] = 0;
        __syncthreads();
        for (int e = tid; e < NAC; e += NTHR)
            atomicAdd(&hist[(u32)(keys[e] >> 52)], 1u);
        __syncthreads();
        u32 B = find_bin4k(hist, (unsigned)PRE, wsum, &s_bin);
        __syncthreads();
        for (int i = tid; i < 4096; i += NTHR) s.tk.buf[i] = ~0ull;
        if (tid == 0) scnt = 0;
        __syncthreads();
        for (int e = tid; e < NAC; e += NTHR){
            u64 key = keys[e];
            if ((u32)(key >> 52) <= B){
                unsigned p = atomicAdd(&scnt, 1u);
                if (p < 4096) s.tk.buf[p] = key;
            }
        }
        __syncthreads();
        if (scnt <= 2048u) bitonic_sort<2048>(s.tk.buf, tid, NTHR);
        else               bitonic_sort<4096>(s.tk.buf, tid, NTHR);
        for (int t = tid; t < PRE; t += NTHR){
            int n = (int)(s.tk.buf[t] & 0xFFFFFFFFull);
            float4 v = *(const float4*)(g_prop + ((size_t)b*NAC + n)*4);
            *(float4*)(g_sbox + ((size_t)b*PRE + t)*4) = v;
        }
    } else {
        int b = (blk - 8) >> 1, c = (blk - 8) & 1;
        int* lab = g_lab + (size_t)b*NAC;
        const u64* R = g_R + (size_t)b*NAC;
        if (tid < NG) s.sel.tmp[tid] = ~0ull;
        __syncthreads();
        for (int i = tid; i < NBLK*NG; i += NTHR){
            int blkI = i / NG, g = i % NG;
            u64 v = g_gtblk[blkI*NB*NG + b*NG + g];
            if (v != ~0ull)
                atomicMin((unsigned long long*)&s.sel.tmp[g], (unsigned long long)v);
        }
        __syncthreads();
        if (tid < NG){
            int n = (int)(s.sel.tmp[tid] & 0xFFFFFFFFull);
            if (!anchor_inside(n)) lab[n] = 1;
        }
        for (int i = tid; i < 4096; i += NTHR) s.sel.hist[i] = 0;
        if (tid == 0) scnt = 0;
        __syncthreads();
        int want = (c == 0) ? 1 : 0;
        int cp = 0, cn = 0;
        for (int e = tid; e < NAC; e += NTHR){
            int l = lab[e];
            cp += (l == 1); cn += (l == 0);
            if (l == want) atomicAdd(&s.sel.hist[(u32)(R[e] >> 43)], 1u);
        }
        #pragma unroll
        for (int o = 16; o > 0; o >>= 1){
            cp += __shfl_down_sync(FULL, cp, o);
            cn += __shfl_down_sync(FULL, cn, o);
        }
        __shared__ int scp, scn;
        if (tid == 0){ scp = 0; scn = 0; }
        __syncthreads();
        if (lane == 0){ atomicAdd(&scp, cp); atomicAdd(&scn, cn); }
        __syncthreads();
        int np = min(scp, 128);
        int nn = min(scn, 256 - np);
        unsigned k = (c == 0) ? (unsigned)np : (unsigned)nn;
        u64 thr = 0;
        if (k > 0){
            u32 B = find_bin4k(s.sel.hist, k, wsum, &s_bin);
            for (int i = tid; i < 512; i += NTHR) s.sel.buf[i] = ~0ull;
            __syncthreads();
            for (int e = tid; e < NAC; e += NTHR){
                if (lab[e] != want) continue;
                u64 key = R[e];
                if ((u32)(key >> 43) <= B){
                    unsigned p = atomicAdd(&scnt, 1u);
                    if (p < 512) s.sel.buf[p] = key;
                }
            }
            __syncthreads();
            bitonic_sort<512>(s.sel.buf, tid, NTHR);
            thr = s.sel.buf[k-1];
        }
        if (tid == 0){
            if (c == 0){ g_posthr[b] = thr; g_npos[b] = np; }
            else       { g_negthr[b] = thr; g_nneg[b] = nn; }
        }
    }
}

// ---------------- K3: mask (0-127) | loss (128-147) ------------------------
__global__ void __launch_bounds__(NTHR, 1)
k_p2(const float* __restrict__ pred, const float* __restrict__ cls,
     const float* __restrict__ gt){
    __shared__ union {
        struct { float sx1[PRE], sy1[PRE], sx2[PRE], sy2[PRE]; } mk;
        struct { double s1[NTHR]; double s2[NTHR]; } ls;
    } s;
    int blk = blockIdx.x, tid = threadIdx.x;
    int lane = tid & 31;

    if (blk < MASKB){
        int b = blk >> 4;
        int q = blk & 15;
        const float* sb = g_sbox + (size_t)b*PRE*4;
        for (int j = tid; j < PRE; j += NTHR){
            float4 v = ((const float4*)sb)[j];
            s.mk.sx1[j]=v.x; s.mk.sy1[j]=v.y; s.mk.sx2[j]=v.z; s.mk.sy2[j]=v.w;
        }
        __syncthreads();
        int warp = tid >> 5;
        for (int t = q; t < 63; t += 16){
            int i = t*32 + warp;
            if (i >= PRE) continue;
            float ax1 = s.mk.sx1[i], ay1 = s.mk.sy1[i];
            float ax2 = s.mk.sx2[i], ay2 = s.mk.sy2[i];
            u32* rowout = g_nmsmask + ((size_t)b*PRE + i)*64;
            int cj0 = i >> 5;
            for (int cj = lane; cj < cj0; cj += 32) rowout[cj] = 0u;
            for (int cj = cj0; cj < 63; cj++){
                int j = cj*32 + lane;
                bool bit = false;
                if (j < PRE && j > i){
                    float iou = iou_pair(ax1, ay1, ax2, ay2,
                                         s.mk.sx1[j], s.mk.sy1[j],
                                         s.mk.sx2[j], s.mk.sy2[j]);
                    bit = iou > 0.7f;
                }
                u32 word = __ballot_sync(FULL, bit);
                if (lane == 0) rowout[cj] = word;
            }
            if (lane == 0) rowout[63] = 0u;
        }
    } else {
        int lblk = blk - MASKB;
        const int lstride = NLOSS*NTHR;
        double cacc = 0.0, bacc = 0.0;
        for (int e = lblk*NTHR + tid; e < NTOT; e += lstride){
            int b = e / NAC, n = e - b*NAC;
            int lab0 = g_lab[e];
            u64 R = g_R[e];
            int lab = -1;
            if (lab0 == 1 && g_npos[b] > 0 && R <= g_posthr[b]) lab = 1;
            else if (lab0 == 0 && g_nneg[b] > 0 && R <= g_negthr[b]) lab = 0;
            if (lab == -1) continue;
            int hw = n / 9, a = n % 9, h = hw / 50, w = hw % 50;
            {
                float x0 = cls[(((size_t)b*18 + a*2    )*50 + h)*50 + w];
                float x1 = cls[(((size_t)b*18 + a*2 + 1)*50 + h)*50 + w];
                float m = fmaxf(x0, x1);
                float l = logf(__fadd_rn(expf(__fsub_rn(x0, m)), expf(__fsub_rn(x1, m))));
                float sel = (lab == 1) ? x1 : x0;
                cacc += (double)__fsub_rn(l, __fsub_rn(sel, m));
            }
            if (lab == 1){
                float pd[4];
                size_t pbase = (((size_t)b*36 + (size_t)a*4)*50 + h)*50 + w;
                pd[0]=pred[pbase]; pd[1]=pred[pbase+2500];
                pd[2]=pred[pbase+5000]; pd[3]=pred[pbase+7500];
                float ax, ay, aw, ah; anchor_ctr(n, ax, ay, aw, ah);
                int gi = g_arg[e];
                const float* g4 = gt + ((size_t)b*NG + gi)*4;
                float gx = __fmul_rn(__fadd_rn(g4[0], g4[2]), 0.5f);
                float gy = __fmul_rn(__fadd_rn(g4[1], g4[3]), 0.5f);
                float gw = __fsub_rn(g4[2], g4[0]);
                float gh = __fsub_rn(g4[3], g4[1]);
                float tt[4];
                tt[0] = __fdiv_rn(__fsub_rn(gx, ax), aw);
                tt[1] = __fdiv_rn(__fsub_rn(gy, ay), ah);
                tt[2] = logf(__fdiv_rn(gw, aw));
                tt[3] = logf(__fdiv_rn(gh, ah));
                const float C1 = (float)(1.0/9.0), C2 = (float)(0.5/9.0);
                double sacc = 0.0;
                #pragma unroll
                for (int k2 = 0; k2 < 4; k2++){
                    float d = __fsub_rn(pd[k2], tt[k2]);
                    float ad = fabsf(d);
                    float l1 = (ad < C1) ? __fmul_rn(__fmul_rn(4.5f, d), d) : __fsub_rn(ad, C2);
                    sacc += (double)l1;
                }
                bacc += sacc;
            }
        }
        s.ls.s1[tid] = cacc; s.ls.s2[tid] = bacc;
        __syncthreads();
        for (int o = NTHR/2; o > 0; o >>= 1){
            if (tid < o){ s.ls.s1[tid] += s.ls.s1[tid+o]; s.ls.s2[tid] += s.ls.s2[tid+o]; }
            __syncthreads();
        }
        if (tid == 0){ g_partC[lblk] = s.ls.s1[0]; g_partB[lblk] = s.ls.s2[0]; }
    }
}

// ---------------- K4: windowed double-buffered NMS walk (0-7) | lossfin ----
// 32 windows of 64 boxes. Warps 1-7 bulk-load window w+1's 64 rows into the
// alternate smem buffer; warp 0 serially walks window w from smem. One
// __syncthreads per window; early-exit flag checked uniformly after sync.
__global__ void __launch_bounds__(256, 1)
k_p3(float* __restrict__ out){
    __shared__ u32 rbuf[2][64][64];   // 32 KB: [parity][row-in-window][u32]
    __shared__ int skeep[POST];
    __shared__ int s_done;
    int blk = blockIdx.x, tid = threadIdx.x;
    int wid = tid >> 5, lane = tid & 31;

    if (blk < NB){
        int b = blk;
        const u32* mbase = g_nmsmask + (size_t)b*PRE*64;
        if (tid == 0) s_done = 0;

        // prologue: all 8 warps load window 0 (rows 0..63)
        for (int l = wid; l < 64; l += 8){
            u64 v = __ldg((const u64*)(mbase + (size_t)l*64) + lane);
            *(u64*)&rbuf[0][l][2*lane] = v;
        }
        __syncthreads();

        u64 rem = (lane == 31) ? ~((1ull << (PRE - 1984)) - 1ull) : 0ull;
        int cnt = 0;

        for (int w = 0; w < NWIN; w++){
            if (wid > 0){
                // load window w+1 rows into alternate buffer
                int wn = w + 1;
                if (wn < NWIN){
                    for (int l = wid - 1; l < 64; l += 7){
                        int r = wn*64 + l;
                        if (r < PRE){
                            u64 v = __ldg((const u64*)(mbase + (size_t)r*64) + lane);
                            *(u64*)&rbuf[wn & 1][l][2*lane] = v;
                        }
                    }
                }
            } else {
                // warp 0: serial greedy over window w from smem
                u64 word = __shfl_sync(FULL, rem, w);   // window w == lane w's u64
                u64 cand = ~word;
                while (cand != 0ull && cnt < POST){
                    int bit = __ffsll((long long)cand) - 1;
                    int i = w*64 + bit;
                    if (lane == 0) skeep[cnt] = i;
                    cnt++;
                    if (cnt >= POST) break;
                    u64 m = *(const u64*)&rbuf[w & 1][bit][2*lane];
                    rem |= m;
                    u64 neww = __shfl_sync(FULL, rem, w);
                    u64 below = (bit == 63) ? ~0ull : ((2ull << bit) - 1ull);
                    cand = ~neww & ~below;
                }
                if (cnt >= POST && lane == 0) s_done = 1;
            }
            __syncthreads();
            if (s_done) break;
        }

        // warp 0 writes outputs
        if (wid == 0){
            for (int j = lane; j < POST; j += 32){
                float4 v = make_float4(0.f, 0.f, 0.f, 0.f);
                if (j < cnt){
                    int i = skeep[j];
                    const float4 p = *(const float4*)(g_sbox + ((size_t)b*PRE + i)*4);
                    v = make_float4(floorf(p.x), floorf(p.y), floorf(p.z), floorf(p.w));
                }
                ((float4*)out)[b*POST + j] = v;
            }
        }
    } else if (tid == 0){
        double a = 0.0, c = 0.0;
        for (int i = 0; i < NLOSS; i++){ a += g_partC[i]; c += g_partB[i]; }
        int tot = 0;
        for (int b = 0; b < NB; b++) tot += g_npos[b] + g_nneg[b];
        if (tot < 1) tot = 1;
        int N0 = g_npos[0] + g_nneg[0];
        if (N0 < 1) N0 = 1;
        out[NB*POST*4 + 0] = (float)(c / (double)N0);   // bbox_loss
        out[NB*POST*4 + 1] = (float)(a / (double)tot);  // cls_loss
    }
}

// ---------------- launch: 4 kernels ----------------------------------------
extern "C" void kernel_launch(void* const* d_in, const int* in_sizes, int n_in,
                              void* d_out, int out_size){
    const float* pred = (const float*)d_in[0];
    const float* cls  = (const float*)d_in[1];
    const float* gt   = (const float*)d_in[2];
    float* out = (float*)d_out;
    (void)in_sizes; (void)n_in; (void)out_size;

    k_p0<<<NBLK, NTHR>>>(pred, cls, gt);
    k_p1<<<24, NTHR>>>();
    k_p2<<<NBLK, NTHR>>>(pred, cls, gt);
    k_p3<<<NB + 1, 256>>>(out);
}